// round 2
// baseline (speedup 1.0000x reference)
#include <cuda_runtime.h>
#include <cstdint>
#include <cstddef>

#define TT 2048
#define BB 32
#define HH 256
#define NCTA 64

// ---------------- global scratch (allocation-free: __device__ globals) ----------
__device__ float g_gi[(size_t)TT * BB * 3 * HH];   // precomputed x @ w_ih^T + b_ih  [T][B][768]
__device__ float g_h[2][BB * HH];                  // double-buffered hidden state
__device__ unsigned g_bar_count;
__device__ unsigned g_bar_epoch;

// ---------------- grid barrier (graph-safe, replay-safe via epoch base) --------
__device__ __forceinline__ void grid_barrier(unsigned target) {
  __syncthreads();
  if (threadIdx.x == 0) {
    __threadfence();
    unsigned prev = atomicAdd(&g_bar_count, 1u);
    if (prev == gridDim.x - 1) {
      atomicExch(&g_bar_count, 0u);
      __threadfence();
      atomicExch(&g_bar_epoch, target);
    } else {
      while ((int)(*(volatile unsigned*)&g_bar_epoch - target) < 0) {}
      __threadfence();
    }
  }
  __syncthreads();
}

// ---------------- gi precompute: g_gi[t][b][g] = x_t[b]·w_ih[g] + b_ih[g] -------
__global__ __launch_bounds__(256) void gi_kernel(
    const float* __restrict__ x, const float* __restrict__ w_ih,
    const float* __restrict__ b_ih) {
  __shared__ float xs[32 * 260];    // x_t tile, padded stride 260
  __shared__ float ws[128 * 20];    // w tile 128 rows x 16 k, padded stride 20
  const int t   = blockIdx.x;
  const int gc0 = blockIdx.y * 128;
  const int tid = threadIdx.x;

  // load x_t : input is [B, T, H]
  for (int i = tid; i < 2048; i += 256) {
    int b = i >> 6;
    int c4 = (i & 63) << 2;
    float4 v = *(const float4*)(x + ((size_t)b * TT + t) * HH + c4);
    *(float4*)(xs + b * 260 + c4) = v;
  }

  const int bq = tid >> 5;   // warp id -> batch base bq*4
  const int gq = tid & 31;   // owns rows gq + 32*j

  float acc[4][4];
#pragma unroll
  for (int i = 0; i < 4; i++)
#pragma unroll
    for (int j = 0; j < 4; j++) acc[i][j] = 0.f;

  for (int kt = 0; kt < 16; ++kt) {
    const int k0 = kt * 16;
    __syncthreads();  // prior compute done before ws overwrite
    for (int i = tid; i < 512; i += 256) {  // 128 rows x 4 float4
      int r = i >> 2;
      int c4 = (i & 3) << 2;
      *(float4*)(ws + r * 20 + c4) =
          *(const float4*)(w_ih + (size_t)(gc0 + r) * HH + k0 + c4);
    }
    __syncthreads();
#pragma unroll
    for (int q = 0; q < 4; ++q) {
      const int kk = q << 2;
      float4 wv[4];
#pragma unroll
      for (int j = 0; j < 4; j++)
        wv[j] = *(const float4*)(ws + (gq + 32 * j) * 20 + kk);
#pragma unroll
      for (int i = 0; i < 4; i++) {
        float4 xv = *(const float4*)(xs + (bq * 4 + i) * 260 + k0 + kk);
#pragma unroll
        for (int j = 0; j < 4; j++) {
          acc[i][j] += xv.x * wv[j].x + xv.y * wv[j].y +
                       xv.z * wv[j].z + xv.w * wv[j].w;
        }
      }
    }
  }
#pragma unroll
  for (int j = 0; j < 4; j++) {
    int g = gc0 + gq + 32 * j;
    float bias = b_ih[g];
#pragma unroll
    for (int i = 0; i < 4; i++) {
      int b = bq * 4 + i;
      g_gi[((size_t)t * BB + b) * 768 + g] = acc[i][j] + bias;
    }
  }
}

// ---------------- persistent recurrent scan ------------------------------------
// 64 CTAs, each owns 4 hidden columns -> 12 gate rows of w_hh kept in SMEM.
// Per cell: load h (32x256) to SMEM, compute gh for owned rows (K split 8-way
// across warps, 4 batches x 3 gates per thread), combine, gates, write h_new.
__global__ __launch_bounds__(256) void scan_kernel(
    const float* __restrict__ hidden, const float* __restrict__ w_hh,
    const float* __restrict__ b_hh, float* __restrict__ out) {
  extern __shared__ float sm[];
  float* h_s   = sm;          // 32 x 264
  float* w_s   = sm + 8448;   // 12 x 264
  float* part  = w_s + 3168;  // [8 kh][32 b][4 j][3 g]
  float* bhh_s = part + 3072; // 12 (+4 pad)
  __shared__ unsigned s_ep0;

  const int tid = threadIdx.x;
  const int c   = blockIdx.x;

  if (tid == 0) s_ep0 = atomicAdd(&g_bar_epoch, 0u);

  // persistent w_hh slice: rows {g*256 + c*4 + j} for g in 0..2, j in 0..3
  for (int i = tid; i < 768; i += 256) {      // 12 rows x 64 float4
    int r  = i >> 6;
    int c4 = (i & 63) << 2;
    *(float4*)(w_s + r * 264 + c4) =
        *(const float4*)(w_hh + (size_t)((r >> 2) * HH + c * 4 + (r & 3)) * HH + c4);
  }
  if (tid < 12) bhh_s[tid] = b_hh[(tid >> 2) * HH + c * 4 + (tid & 3)];
  if (tid < 128) {  // init own columns of h
    int b = tid >> 2, j = tid & 3;
    int col = c * 4 + j;
    g_h[0][b * HH + col] = hidden[b * HH + col];
  }
  __syncthreads();
  unsigned ep = s_ep0;
  ++ep;
  grid_barrier(ep);

  const int kh   = tid >> 5;   // 8-way K split (K=32 per warp)
  const int lane = tid & 31;
  const int bq   = lane >> 2;  // batches bq, bq+8, bq+16, bq+24
  const int jj   = lane & 3;   // local column

  int cur = 0;
  for (int step = 0; step < TT; ++step) {
    const float* gi_t = g_gi + (size_t)step * BB * 768;
    for (int layer = 0; layer < 2; ++layer) {
      // load full h into SMEM (bypass L1: written by other SMs last cell)
      for (int i = tid; i < 2048; i += 256) {
        int b  = i >> 6;
        int c4 = (i & 63) << 2;
        float4 v = __ldcg((const float4*)(g_h[cur] + b * HH + c4));
        *(float4*)(h_s + b * 264 + c4) = v;
      }
      // prefetch gi for epilogue threads (hide DRAM/L2 latency behind k-loop)
      float gir = 0.f, giz = 0.f, gin = 0.f;
      if (tid < 128) {
        int b = tid >> 2, j2 = tid & 3;
        const float* gp = gi_t + b * 768 + c * 4 + j2;
        gir = gp[0];
        giz = gp[256];
        gin = gp[512];
      }
      __syncthreads();

      float acc[4][3];
#pragma unroll
      for (int bi = 0; bi < 4; ++bi)
#pragma unroll
        for (int g = 0; g < 3; ++g) acc[bi][g] = 0.f;

      const int k0 = kh * 32;
#pragma unroll
      for (int q = 0; q < 8; ++q) {
        const int k = k0 + (q << 2);
        const float4 wr = *(const float4*)(w_s + (jj)     * 264 + k);
        const float4 wz = *(const float4*)(w_s + (4 + jj) * 264 + k);
        const float4 wn = *(const float4*)(w_s + (8 + jj) * 264 + k);
#pragma unroll
        for (int bi = 0; bi < 4; ++bi) {
          const float4 hv = *(const float4*)(h_s + (bq + bi * 8) * 264 + k);
          acc[bi][0] += hv.x * wr.x + hv.y * wr.y + hv.z * wr.z + hv.w * wr.w;
          acc[bi][1] += hv.x * wz.x + hv.y * wz.y + hv.z * wz.z + hv.w * wz.w;
          acc[bi][2] += hv.x * wn.x + hv.y * wn.y + hv.z * wn.z + hv.w * wn.w;
        }
      }
#pragma unroll
      for (int bi = 0; bi < 4; ++bi) {
        float* p = part + ((kh * 32) + bq + bi * 8) * 12 + jj * 3;
        p[0] = acc[bi][0];
        p[1] = acc[bi][1];
        p[2] = acc[bi][2];
      }
      __syncthreads();

      const int nxt = cur ^ 1;
      if (tid < 128) {
        int b = tid >> 2, j2 = tid & 3;
        int col = c * 4 + j2;
        float ghr = 0.f, ghz = 0.f, ghn = 0.f;
#pragma unroll
        for (int k2 = 0; k2 < 8; ++k2) {
          const float* p = part + (k2 * 32 + b) * 12 + j2 * 3;
          ghr += p[0];
          ghz += p[1];
          ghn += p[2];
        }
        ghr += bhh_s[j2];
        ghz += bhh_s[4 + j2];
        ghn += bhh_s[8 + j2];
        float r = 1.f / (1.f + expf(-(gir + ghr)));
        float z = 1.f / (1.f + expf(-(giz + ghz)));
        float n = tanhf(gin + r * ghn);
        float hold = h_s[b * 264 + col];
        float hn = (1.f - z) * n + z * hold;
        g_h[nxt][b * HH + col] = hn;
        if (layer == 1) out[((size_t)step * BB + b) * HH + col] = hn;
      }
      cur = nxt;
      ++ep;
      grid_barrier(ep);
    }
  }
}

// ---------------- launch --------------------------------------------------------
extern "C" void kernel_launch(void* const* d_in, const int* in_sizes, int n_in,
                              void* d_out, int out_size) {
  const float *input = 0, *hidden = 0, *w_ih = 0, *w_hh = 0, *b_ih = 0, *b_hh = 0;
  for (int i = 0; i < n_in; ++i) {
    long s = in_sizes[i];
    if (s == (long)BB * TT * HH) {
      input = (const float*)d_in[i];
    } else if (s == BB * HH && !hidden) {
      hidden = (const float*)d_in[i];
    } else if (s == 3 * HH * HH) {
      if (!w_ih) w_ih = (const float*)d_in[i]; else w_hh = (const float*)d_in[i];
    } else if (s == 3 * HH) {
      if (!b_ih) b_ih = (const float*)d_in[i]; else b_hh = (const float*)d_in[i];
    }
  }
  cudaFuncSetAttribute(scan_kernel, cudaFuncAttributeMaxDynamicSharedMemorySize, 58816);
  gi_kernel<<<dim3(TT, 6), 256>>>(input, w_ih, b_ih);
  scan_kernel<<<NCTA, 256, 58816>>>(hidden, w_hh, b_hh, (float*)d_out);
}